// round 4
// baseline (speedup 1.0000x reference)
#include <cuda_runtime.h>

// Problem constants: imgs (64, 3, 512, 512) f32, xform_params (64, 2) f32.
constexpr int BATCH = 64;
constexpr int HW    = 512 * 512;      // 262144 pixels per channel plane
constexpr int VEC   = HW / 4;         // 65536 float4 vectors per plane
constexpr int THREADS = 256;

__device__ __forceinline__ float mod_pos(float x, float y) {
    // Python/jnp.mod semantics: result in [0, y) for y > 0.
    float r = fmodf(x, y);
    return (r < 0.0f) ? r + y : r;
}

__device__ __forceinline__ float clip01(float x) {
    return fminf(fmaxf(x, 0.0f), 1.0f);
}

__device__ __forceinline__ void adjust_pixel(float r, float g, float b,
                                             float dh, float ds,
                                             float& ro, float& go, float& bo) {
    // ---- rgb2hsv ----
    float maxc = fmaxf(r, fmaxf(g, b));
    float minc = fminf(r, fminf(g, b));
    bool  eqc  = (maxc == minc);
    float cr   = maxc - minc;
    float s    = cr / (eqc ? 1.0f : maxc);
    float crd  = eqc ? 1.0f : cr;
    float inv  = 1.0f / crd;
    float rc = (maxc - r) * inv;
    float gc = (maxc - g) * inv;
    float bc = (maxc - b) * inv;

    bool is_r = (maxc == r);
    bool is_g = (maxc == g) && !is_r;
    bool is_b = (maxc != g) && !is_r;

    float hsum = (is_r ? (bc - gc) : 0.0f)
               + (is_g ? (2.0f + rc - bc) : 0.0f)
               + (is_b ? (4.0f + gc - rc) : 0.0f);
    float h = mod_pos(hsum, 6.0f) * (1.0f / 6.0f);
    float v = maxc;

    // ---- adjust ----
    h = mod_pos(h + dh, 1.0f);
    s = clip01(s * ds);

    // ---- hsv2rgb ----
    float h6 = h * 6.0f;
    float fi = floorf(h6);
    float f  = h6 - fi;
    int   i  = ((int)fi) % 6;   // fi >= 0 here, so % is fine

    float p = clip01(v * (1.0f - s));
    float q = clip01(v * (1.0f - s * f));
    float t = clip01(v * (1.0f - s * (1.0f - f)));

    switch (i) {
        case 0: ro = v; go = t; bo = p; break;
        case 1: ro = q; go = v; bo = p; break;
        case 2: ro = p; go = v; bo = t; break;
        case 3: ro = p; go = q; bo = v; break;
        case 4: ro = t; go = p; bo = v; break;
        default: ro = v; go = p; bo = q; break;
    }
}

__global__ void __launch_bounds__(THREADS)
adjust_hue_sat_kernel(const float* __restrict__ img,
                      const float* __restrict__ xp,
                      float* __restrict__ out) {
    int vi = blockIdx.x * THREADS + threadIdx.x;   // vector index in [0, BATCH*VEC)
    int b  = vi >> 16;                              // vi / VEC (VEC = 65536)
    int off = (vi & (VEC - 1)) << 2;                // pixel offset within plane

    float dh = __ldg(&xp[2 * b + 0]);
    float ds = __ldg(&xp[2 * b + 1]);

    size_t base = (size_t)b * 3 * HW + off;
    float4 r4 = *reinterpret_cast<const float4*>(img + base);
    float4 g4 = *reinterpret_cast<const float4*>(img + base + HW);
    float4 b4 = *reinterpret_cast<const float4*>(img + base + 2 * HW);

    float ri[4] = {r4.x, r4.y, r4.z, r4.w};
    float gi[4] = {g4.x, g4.y, g4.z, g4.w};
    float bi[4] = {b4.x, b4.y, b4.z, b4.w};
    float ro[4], go[4], bo[4];

    #pragma unroll
    for (int k = 0; k < 4; k++) {
        adjust_pixel(ri[k], gi[k], bi[k], dh, ds, ro[k], go[k], bo[k]);
    }

    float4 r_out = make_float4(ro[0], ro[1], ro[2], ro[3]);
    float4 g_out = make_float4(go[0], go[1], go[2], go[3]);
    float4 b_out = make_float4(bo[0], bo[1], bo[2], bo[3]);

    *reinterpret_cast<float4*>(out + base)          = r_out;
    *reinterpret_cast<float4*>(out + base + HW)     = g_out;
    *reinterpret_cast<float4*>(out + base + 2 * HW) = b_out;
}

extern "C" void kernel_launch(void* const* d_in, const int* in_sizes, int n_in,
                              void* d_out, int out_size) {
    const float* img = (const float*)d_in[0];
    const float* xp  = (const float*)d_in[1];
    float* out = (float*)d_out;

    int total_vec = BATCH * VEC;                 // 4,194,304 threads
    int blocks = total_vec / THREADS;            // 16,384 blocks
    adjust_hue_sat_kernel<<<blocks, THREADS>>>(img, xp, out);
}

// round 5
// speedup vs baseline: 1.0909x; 1.0909x over previous
#include <cuda_runtime.h>

// Problem constants: imgs (64, 3, 512, 512) f32, xform_params (64, 2) f32.
constexpr int BATCH = 64;
constexpr int HW    = 512 * 512;      // 262144 pixels per channel plane
constexpr int VEC   = HW / 4;         // 65536 float4 vectors per plane
constexpr int THREADS = 256;

__device__ __forceinline__ float clip01(float x) {
    return fminf(fmaxf(x, 0.0f), 1.0f);
}

// One hue-to-rgb channel: v - v*s*clamp(min(k, 4-k), 0, 1), k = (h6 + n) mod 6.
// h6 in [0,6], n in {5,3,1} -> h6+n in [1,11]; one conditional -6 suffices.
__device__ __forceinline__ float hue_chan(float h6, float n, float v, float vs) {
    float k = h6 + n;
    k = (k >= 6.0f) ? k - 6.0f : k;
    float m = clip01(fminf(k, 4.0f - k));
    return fmaf(-vs, m, v);   // v * (1 - s*m)
}

__device__ __forceinline__ void adjust_pixel(float r, float g, float b,
                                             float dh6, float ds,
                                             float& ro, float& go, float& bo) {
    // ---- rgb2hsv (hue in sextant units, h6 in [0,6)) ----
    float maxc = fmaxf(r, fmaxf(g, b));
    float minc = fminf(r, fminf(g, b));
    float cr   = maxc - minc;
    bool  eqc  = (cr == 0.0f);

    float s   = cr / (eqc ? 1.0f : maxc);
    float inv = 1.0f / (eqc ? 1.0f : cr);

    bool is_r = (maxc == r);
    bool is_g = (maxc == g);

    // bc-gc = (g-b)*inv ; 2+rc-bc = 2+(b-r)*inv ; 4+gc-rc = 4+(r-g)*inv
    float hsum = is_r ? (g - b) * inv
               : (is_g ? fmaf(b - r, inv, 2.0f)
                       : fmaf(r - g, inv, 4.0f));      // in [-1, 5]

    // ---- fused hue shift + mod 6 (replaces two fmodf) ----
    float h6 = hsum + dh6;                 // in [-4, 8)
    h6 = (h6 < 0.0f)  ? h6 + 6.0f : h6;
    h6 = (h6 >= 6.0f) ? h6 - 6.0f : h6;    // in [0, 6]

    // ---- saturation adjust ----
    s = clip01(s * ds);
    float v  = maxc;
    float vs = v * s;

    // ---- hsv2rgb, branchless ----
    ro = hue_chan(h6, 5.0f, v, vs);
    go = hue_chan(h6, 3.0f, v, vs);
    bo = hue_chan(h6, 1.0f, v, vs);
}

__global__ void __launch_bounds__(THREADS)
adjust_hue_sat_kernel(const float* __restrict__ img,
                      const float* __restrict__ xp,
                      float* __restrict__ out) {
    int vi = blockIdx.x * THREADS + threadIdx.x;   // vector index in [0, BATCH*VEC)
    int b  = vi >> 16;                              // vi / VEC (VEC = 65536)
    int off = (vi & (VEC - 1)) << 2;                // pixel offset within plane

    float dh6 = __ldg(&xp[2 * b + 0]) * 6.0f;
    float ds  = __ldg(&xp[2 * b + 1]);

    size_t base = (size_t)b * 3 * HW + off;
    float4 r4 = __ldcs(reinterpret_cast<const float4*>(img + base));
    float4 g4 = __ldcs(reinterpret_cast<const float4*>(img + base + HW));
    float4 b4 = __ldcs(reinterpret_cast<const float4*>(img + base + 2 * HW));

    float ri[4] = {r4.x, r4.y, r4.z, r4.w};
    float gi[4] = {g4.x, g4.y, g4.z, g4.w};
    float bi[4] = {b4.x, b4.y, b4.z, b4.w};
    float ro[4], go[4], bo[4];

    #pragma unroll
    for (int k = 0; k < 4; k++) {
        adjust_pixel(ri[k], gi[k], bi[k], dh6, ds, ro[k], go[k], bo[k]);
    }

    float4 r_out = make_float4(ro[0], ro[1], ro[2], ro[3]);
    float4 g_out = make_float4(go[0], go[1], go[2], go[3]);
    float4 b_out = make_float4(bo[0], bo[1], bo[2], bo[3]);

    __stcs(reinterpret_cast<float4*>(out + base),          r_out);
    __stcs(reinterpret_cast<float4*>(out + base + HW),     g_out);
    __stcs(reinterpret_cast<float4*>(out + base + 2 * HW), b_out);
}

extern "C" void kernel_launch(void* const* d_in, const int* in_sizes, int n_in,
                              void* d_out, int out_size) {
    const float* img = (const float*)d_in[0];
    const float* xp  = (const float*)d_in[1];
    float* out = (float*)d_out;

    int total_vec = BATCH * VEC;                 // 4,194,304 threads
    int blocks = total_vec / THREADS;            // 16,384 blocks
    adjust_hue_sat_kernel<<<blocks, THREADS>>>(img, xp, out);
}

// round 6
// speedup vs baseline: 1.0948x; 1.0035x over previous
#include <cuda_runtime.h>

// Problem constants: imgs (64, 3, 512, 512) f32, xform_params (64, 2) f32.
constexpr int BATCH = 64;
constexpr int HW    = 512 * 512;      // 262144 pixels per channel plane
constexpr int VEC   = HW / 4;         // 65536 float4 vectors per plane
constexpr int THREADS = 256;
constexpr int PER    = 2;             // float4 vectors per thread per channel
constexpr int BLOCK_VECS = THREADS * PER;   // 512 vectors per block (fits in one plane)

__device__ __forceinline__ float clip01(float x) {
    return fminf(fmaxf(x, 0.0f), 1.0f);
}

// One hue-to-rgb channel: v - vs*clamp(min(k, 4-k), 0, 1), k = (h6 + n) mod 6.
// h6 in [0,6], n in {5,3,1} -> h6+n in [1,11]; one conditional -6 suffices.
__device__ __forceinline__ float hue_chan(float h6, float n, float v, float vs) {
    float k = h6 + n;
    k = (k >= 6.0f) ? k - 6.0f : k;
    float m = clip01(fminf(k, 4.0f - k));
    return fmaf(-vs, m, v);   // v * (1 - s*m)
}

__device__ __forceinline__ void adjust_pixel(float r, float g, float b,
                                             float dh6, float ds,
                                             float& ro, float& go, float& bo) {
    // ---- rgb2hsv (hue in sextant units) ----
    float maxc = fmaxf(r, fmaxf(g, b));
    float minc = fminf(r, fminf(g, b));
    float cr   = maxc - minc;
    float crd  = (cr == 0.0f) ? 1.0f : cr;
    float inv  = __fdividef(1.0f, crd);    // MUFU.RCP path, <=2 ulp

    bool is_r = (maxc == r);
    bool is_g = (maxc == g);

    // bc-gc = (g-b)*inv ; 2+rc-bc = 2+(b-r)*inv ; 4+gc-rc = 4+(r-g)*inv
    float hsum = is_r ? (g - b) * inv
               : (is_g ? fmaf(b - r, inv, 2.0f)
                       : fmaf(r - g, inv, 4.0f));      // in [-1, 5]

    // ---- fused hue shift + mod 6 ----
    float h6 = hsum + dh6;                 // in [-4, 8)
    h6 = (h6 < 0.0f)  ? h6 + 6.0f : h6;
    h6 = (h6 >= 6.0f) ? h6 - 6.0f : h6;    // in [0, 6]

    // ---- saturation adjust, algebraically fused ----
    // vs = v * clip01((cr/maxc)*ds) == min(cr*ds, maxc)   (s >= 0 always)
    float v  = maxc;
    float vs = fminf(cr * ds, maxc);

    // ---- hsv2rgb, branchless ----
    ro = hue_chan(h6, 5.0f, v, vs);
    go = hue_chan(h6, 3.0f, v, vs);
    bo = hue_chan(h6, 1.0f, v, vs);
}

__device__ __forceinline__ void process_vec(float4 r4, float4 g4, float4 b4,
                                            float dh6, float ds,
                                            float4& r_out, float4& g_out, float4& b_out) {
    float ri[4] = {r4.x, r4.y, r4.z, r4.w};
    float gi[4] = {g4.x, g4.y, g4.z, g4.w};
    float bi[4] = {b4.x, b4.y, b4.z, b4.w};
    float ro[4], go[4], bo[4];
    #pragma unroll
    for (int k = 0; k < 4; k++)
        adjust_pixel(ri[k], gi[k], bi[k], dh6, ds, ro[k], go[k], bo[k]);
    r_out = make_float4(ro[0], ro[1], ro[2], ro[3]);
    g_out = make_float4(go[0], go[1], go[2], go[3]);
    b_out = make_float4(bo[0], bo[1], bo[2], bo[3]);
}

__global__ void __launch_bounds__(THREADS)
adjust_hue_sat_kernel(const float* __restrict__ img,
                      const float* __restrict__ xp,
                      float* __restrict__ out) {
    // Each block covers BLOCK_VECS=512 consecutive float4 vectors (one batch).
    int vi0 = blockIdx.x * BLOCK_VECS + threadIdx.x;
    int b   = vi0 >> 16;                            // vi0 / VEC (VEC = 65536)
    int off0 = (vi0 & (VEC - 1)) << 2;              // pixel offset within plane

    float dh6 = __ldg(&xp[2 * b + 0]) * 6.0f;
    float ds  = __ldg(&xp[2 * b + 1]);

    size_t base0 = (size_t)b * 3 * HW + off0;
    size_t base1 = base0 + THREADS * 4;             // second vector, same plane

    // Front-batch all 6 loads for maximum MLP.
    float4 r0 = __ldcs(reinterpret_cast<const float4*>(img + base0));
    float4 g0 = __ldcs(reinterpret_cast<const float4*>(img + base0 + HW));
    float4 b0 = __ldcs(reinterpret_cast<const float4*>(img + base0 + 2 * HW));
    float4 r1 = __ldcs(reinterpret_cast<const float4*>(img + base1));
    float4 g1 = __ldcs(reinterpret_cast<const float4*>(img + base1 + HW));
    float4 b1 = __ldcs(reinterpret_cast<const float4*>(img + base1 + 2 * HW));

    float4 ro, go, bo;
    process_vec(r0, g0, b0, dh6, ds, ro, go, bo);
    __stcs(reinterpret_cast<float4*>(out + base0),          ro);
    __stcs(reinterpret_cast<float4*>(out + base0 + HW),     go);
    __stcs(reinterpret_cast<float4*>(out + base0 + 2 * HW), bo);

    process_vec(r1, g1, b1, dh6, ds, ro, go, bo);
    __stcs(reinterpret_cast<float4*>(out + base1),          ro);
    __stcs(reinterpret_cast<float4*>(out + base1 + HW),     go);
    __stcs(reinterpret_cast<float4*>(out + base1 + 2 * HW), bo);
}

extern "C" void kernel_launch(void* const* d_in, const int* in_sizes, int n_in,
                              void* d_out, int out_size) {
    const float* img = (const float*)d_in[0];
    const float* xp  = (const float*)d_in[1];
    float* out = (float*)d_out;

    int total_vec = BATCH * VEC;                     // 4,194,304 float4 vectors
    int blocks = total_vec / BLOCK_VECS;             // 8,192 blocks
    adjust_hue_sat_kernel<<<blocks, THREADS>>>(img, xp, out);
}